// round 1
// baseline (speedup 1.0000x reference)
#include <cuda_runtime.h>
#include <math.h>

#define NBATCH 4
#define TSEQ   4096
#define DMODEL 1024
#define HSIZE  128
#define NROWS  (NBATCH * TSEQ)

// Scratch for q, k, v projections (no dynamic allocation allowed).
__device__ float g_q[(size_t)NROWS * HSIZE];
__device__ float g_k[(size_t)NROWS * HSIZE];
__device__ float g_v[(size_t)NROWS * HSIZE];

// ---------------------------------------------------------------------------
// Kernel 1: fused QKV projection.  out[row,h] = sum_c x[row,c] * W[h,c]
// GEMM M=16384, N=128 (x3 weights via blockIdx.y), K=1024.
// BM=64, BN=128, BK=16; 256 threads; 8x4 micro-tile per thread.
// ---------------------------------------------------------------------------
__global__ __launch_bounds__(256) void qkv_kernel(
    const float* __restrict__ x,
    const float* __restrict__ Wq,
    const float* __restrict__ Wk,
    const float* __restrict__ Wv)
{
    constexpr int BM = 64, BK = 16;
    __shared__ __align__(16) float As[BK][BM + 4];    // [k][m] transposed
    __shared__ __align__(16) float Bs[BK][128 + 4];   // [k][n] transposed

    const float* __restrict__ W =
        (blockIdx.y == 0) ? Wq : ((blockIdx.y == 1) ? Wk : Wv);
    float* out = (blockIdx.y == 0) ? g_q : ((blockIdx.y == 1) ? g_k : g_v);

    const int row0 = blockIdx.x * BM;
    const int t  = threadIdx.x;
    const int tm = (t >> 5) * 8;     // row group (warp-uniform)
    const int tn = (t & 31) * 4;     // col group

    const int ar = t >> 2, ac = (t & 3) * 4;   // A-tile load coords

    float acc[8][4];
#pragma unroll
    for (int i = 0; i < 8; i++)
#pragma unroll
        for (int j = 0; j < 4; j++) acc[i][j] = 0.f;

    for (int k0 = 0; k0 < DMODEL; k0 += BK) {
        // Load A tile 64x16 (one float4 per thread), store transposed.
        {
            float4 av = *reinterpret_cast<const float4*>(
                x + (size_t)(row0 + ar) * DMODEL + k0 + ac);
            As[ac + 0][ar] = av.x; As[ac + 1][ar] = av.y;
            As[ac + 2][ar] = av.z; As[ac + 3][ar] = av.w;
        }
        // Load B tile 128x16 (two float4 per thread), store transposed.
#pragma unroll
        for (int i = 0; i < 2; i++) {
            int idx = t + i * 256;
            int br = idx >> 2, bc = (idx & 3) * 4;
            float4 bv = *reinterpret_cast<const float4*>(
                W + (size_t)br * DMODEL + k0 + bc);
            Bs[bc + 0][br] = bv.x; Bs[bc + 1][br] = bv.y;
            Bs[bc + 2][br] = bv.z; Bs[bc + 3][br] = bv.w;
        }
        __syncthreads();

#pragma unroll
        for (int kk = 0; kk < BK; kk++) {
            float4 a0 = *reinterpret_cast<const float4*>(&As[kk][tm]);
            float4 a1 = *reinterpret_cast<const float4*>(&As[kk][tm + 4]);
            float4 b4 = *reinterpret_cast<const float4*>(&Bs[kk][tn]);
            float a[8] = {a0.x, a0.y, a0.z, a0.w, a1.x, a1.y, a1.z, a1.w};
            float bb[4] = {b4.x, b4.y, b4.z, b4.w};
#pragma unroll
            for (int i = 0; i < 8; i++)
#pragma unroll
                for (int j = 0; j < 4; j++)
                    acc[i][j] = fmaf(a[i], bb[j], acc[i][j]);
        }
        __syncthreads();
    }

#pragma unroll
    for (int i = 0; i < 8; i++) {
        float4 v4 = make_float4(acc[i][0], acc[i][1], acc[i][2], acc[i][3]);
        *reinterpret_cast<float4*>(
            out + (size_t)(row0 + tm + i) * HSIZE + tn) = v4;
    }
}

// ---------------------------------------------------------------------------
// Kernel 2: causal flash attention, fp32.
// Grid (64 q-tiles, 4 batches), 256 threads, 64x64 tiles, head dim 128.
// Q and K stored transposed in smem (broadcast/conflict-free inner loops).
// ---------------------------------------------------------------------------
constexpr int QT = 64;     // query tile rows
constexpr int KT = 64;     // key tile rows
constexpr int QP = 72;     // Q transposed pitch (float4 broadcast reads)
constexpr int KP = 66;     // K transposed pitch (float2 reads, ~no conflicts)
constexpr int SP = 65;     // S row pitch (conflict-free column scans)
constexpr int SMEM_FLOATS = 128 * QP + 128 * KP + KT * HSIZE + QT * SP + 3 * QT;

__global__ __launch_bounds__(256) void attn_kernel(float* __restrict__ out)
{
    extern __shared__ __align__(16) float sm[];
    float* Qst  = sm;                    // [c:128][r:QT] pitch QP
    float* Kst  = Qst + 128 * QP;        // [c:128][r:KT] pitch KP
    float* Vs   = Kst + 128 * KP;        // [r:KT][c:128] row-major
    float* Ss   = Vs + KT * HSIZE;       // [r:QT][c:KT]  pitch SP
    float* mrow = Ss + QT * SP;
    float* lrow = mrow + QT;
    float* arow = lrow + QT;

    const int b  = blockIdx.y;
    const int qt = gridDim.x - 1 - blockIdx.x;   // heaviest tiles first
    const int q0 = qt * QT;

    const float* qb = g_q + ((size_t)b * TSEQ + q0) * HSIZE;
    const float* kb = g_k + (size_t)b * TSEQ * HSIZE;
    const float* vb = g_v + (size_t)b * TSEQ * HSIZE;

    const int t   = threadIdx.x;
    const int tm  = (t >> 5) * 8;     // 8 query rows per thread (warp-uniform)
    const int tn4 = (t & 31) * 4;     // 4 head dims per thread (PV/O)
    const int sn  = (t & 31) * 2;     // 2 key cols per thread (S gemm)
    const float rscale = 0.0883883476483184405f;  // 1/sqrt(128)

    // Load Q tile transposed, pre-scaled.
    for (int idx = t; idx < QT * HSIZE; idx += 256) {
        int r = idx >> 7, c = idx & 127;
        Qst[c * QP + r] = qb[idx] * rscale;
    }
    if (t < QT) { mrow[t] = -INFINITY; lrow[t] = 0.f; }

    float o[8][4];
#pragma unroll
    for (int i = 0; i < 8; i++)
#pragma unroll
        for (int j = 0; j < 4; j++) o[i][j] = 0.f;
    __syncthreads();

    for (int j = 0; j <= qt; j++) {
        const float* kt = kb + (size_t)j * KT * HSIZE;
        const float* vt = vb + (size_t)j * KT * HSIZE;
        // K transposed (scalar, coalesced LDG, conflict-free STS).
        for (int idx = t; idx < KT * HSIZE; idx += 256) {
            int r = idx >> 7, c = idx & 127;
            Kst[c * KP + r] = kt[idx];
        }
        // V row-major (vectorized).
        for (int idx = t; idx < KT * HSIZE / 4; idx += 256)
            reinterpret_cast<float4*>(Vs)[idx] =
                reinterpret_cast<const float4*>(vt)[idx];
        __syncthreads();

        // S = Qs @ Ks^T : each thread 8 rows x 2 cols.
        float s0[8], s1[8];
#pragma unroll
        for (int i = 0; i < 8; i++) { s0[i] = 0.f; s1[i] = 0.f; }
#pragma unroll 4
        for (int kk = 0; kk < HSIZE; kk++) {
            float4 a0 = *reinterpret_cast<const float4*>(&Qst[kk * QP + tm]);
            float4 a1 = *reinterpret_cast<const float4*>(&Qst[kk * QP + tm + 4]);
            float2 bb = *reinterpret_cast<const float2*>(&Kst[kk * KP + sn]);
            float a[8] = {a0.x, a0.y, a0.z, a0.w, a1.x, a1.y, a1.z, a1.w};
#pragma unroll
            for (int i = 0; i < 8; i++) {
                s0[i] = fmaf(a[i], bb.x, s0[i]);
                s1[i] = fmaf(a[i], bb.y, s1[i]);
            }
        }

        const bool diag = (j == qt);
#pragma unroll
        for (int i = 0; i < 8; i++) {
            float v0 = s0[i], v1 = s1[i];
            if (diag) {
                if (tm + i < sn)     v0 = -INFINITY;
                if (tm + i < sn + 1) v1 = -INFINITY;
            }
            Ss[(tm + i) * SP + sn]     = v0;
            Ss[(tm + i) * SP + sn + 1] = v1;
        }
        __syncthreads();

        // Online softmax: one thread per query row.
        if (t < QT) {
            int r = t;
            float mold = mrow[r];
            float mx = mold;
#pragma unroll 8
            for (int c = 0; c < KT; c++) mx = fmaxf(mx, Ss[r * SP + c]);
            float alpha = __expf(mold - mx);
            float l = lrow[r] * alpha;
#pragma unroll 8
            for (int c = 0; c < KT; c++) {
                float p = __expf(Ss[r * SP + c] - mx);
                Ss[r * SP + c] = p;
                l += p;
            }
            mrow[r] = mx; lrow[r] = l; arow[r] = alpha;
        }
        __syncthreads();

        // Rescale O, then O += P @ V.
        float al[8];
#pragma unroll
        for (int i = 0; i < 8; i++) al[i] = arow[tm + i];
#pragma unroll
        for (int i = 0; i < 8; i++)
#pragma unroll
            for (int jj = 0; jj < 4; jj++) o[i][jj] *= al[i];

#pragma unroll 4
        for (int s = 0; s < KT; s++) {
            float4 vv = *reinterpret_cast<const float4*>(&Vs[s * HSIZE + tn4]);
#pragma unroll
            for (int i = 0; i < 8; i++) {
                float p = Ss[(tm + i) * SP + s];
                o[i][0] = fmaf(p, vv.x, o[i][0]);
                o[i][1] = fmaf(p, vv.y, o[i][1]);
                o[i][2] = fmaf(p, vv.z, o[i][2]);
                o[i][3] = fmaf(p, vv.w, o[i][3]);
            }
        }
        __syncthreads();
    }

    // Normalize and write.
#pragma unroll
    for (int i = 0; i < 8; i++) {
        float inv = 1.f / lrow[tm + i];
        float4 v4 = make_float4(o[i][0] * inv, o[i][1] * inv,
                                o[i][2] * inv, o[i][3] * inv);
        *reinterpret_cast<float4*>(
            out + ((size_t)b * TSEQ + q0 + tm + i) * HSIZE + tn4) = v4;
    }
}

// ---------------------------------------------------------------------------
extern "C" void kernel_launch(void* const* d_in, const int* in_sizes, int n_in,
                              void* d_out, int out_size)
{
    const float* x  = (const float*)d_in[0];
    const float* Wq = (const float*)d_in[1];
    const float* Wk = (const float*)d_in[2];
    const float* Wv = (const float*)d_in[3];
    float* out = (float*)d_out;

    qkv_kernel<<<dim3(NROWS / 64, 3), 256>>>(x, Wq, Wk, Wv);

    const int smem_bytes = SMEM_FLOATS * (int)sizeof(float);
    cudaFuncSetAttribute(attn_kernel,
                         cudaFuncAttributeMaxDynamicSharedMemorySize,
                         smem_bytes);
    attn_kernel<<<dim3(TSEQ / QT, NBATCH), 256, smem_bytes>>>(out);
}

// round 2
// speedup vs baseline: 3.3552x; 3.3552x over previous
#include <cuda_runtime.h>
#include <math.h>

#define NBATCH 4
#define TSEQ   4096
#define DMODEL 1024
#define HSIZE  128
#define NROWS  (NBATCH * TSEQ)

__device__ float g_q[(size_t)NROWS * HSIZE];
__device__ float g_k[(size_t)NROWS * HSIZE];
__device__ float g_v[(size_t)NROWS * HSIZE];

__device__ __forceinline__ unsigned f2tf(float f) {
    unsigned u;
    asm("cvt.rna.tf32.f32 %0, %1;" : "=r"(u) : "f"(f));
    return u;
}

// D += A(16x8, row) * B(8x8, col), tf32 inputs, f32 accumulate.
__device__ __forceinline__ void mma8(float* c, const unsigned* a, const unsigned* b) {
    asm volatile(
        "mma.sync.aligned.m16n8k8.row.col.f32.tf32.tf32.f32 "
        "{%0,%1,%2,%3},{%4,%5,%6,%7},{%8,%9},{%0,%1,%2,%3};"
        : "+f"(c[0]), "+f"(c[1]), "+f"(c[2]), "+f"(c[3])
        : "r"(a[0]), "r"(a[1]), "r"(a[2]), "r"(a[3]), "r"(b[0]), "r"(b[1]));
}

// ---------------------------------------------------------------------------
// Kernel 1: QKV projection, tf32 tensor cores.
// C[M=16384, N=128] = x[M,1024] * W^T, three weights via blockIdx.x.
// BM=128, BN=128, BK=32; 256 threads; warp grid (2M x 4N), warp tile 64x32.
// Double-buffered smem + 2-tile-ahead register prefetch.
// ---------------------------------------------------------------------------
#define QKV_PITCH 36            // 36 % 32 == 4  -> conflict-free frag reads
#define QKV_BUFW  (128 * QKV_PITCH)

__global__ __launch_bounds__(256, 1) void qkv_kernel(
    const float* __restrict__ x,
    const float* __restrict__ Wq,
    const float* __restrict__ Wk,
    const float* __restrict__ Wv)
{
    extern __shared__ unsigned sm1[];
    unsigned* As = sm1;                 // [2][128][36]
    unsigned* Bs = sm1 + 2 * QKV_BUFW;  // [2][128][36]

    const int w  = blockIdx.x;          // weight index (fastest -> x-tile L2 reuse)
    const int rb = blockIdx.y;
    const float* __restrict__ W = (w == 0) ? Wq : ((w == 1) ? Wk : Wv);
    float* out = (w == 0) ? g_q : ((w == 1) ? g_k : g_v);
    const int row0 = rb * 128;

    const int t = threadIdx.x;
    const int warp = t >> 5, lane = t & 31;
    const int g = lane >> 2, klo = lane & 3;
    const int m0 = (warp >> 2) * 64;    // warp M offset
    const int n0 = (warp & 3) * 32;     // warp N offset

    float C[4][4][4];
#pragma unroll
    for (int a = 0; a < 4; a++)
#pragma unroll
        for (int bb = 0; bb < 4; bb++)
#pragma unroll
            for (int cpos = 0; cpos < 4; cpos++) C[a][bb][cpos] = 0.f;

    float4 ra[4], rbv[4];

#define QKV_LOADG(kt)                                                          \
    {                                                                          \
        int k0_ = (kt) * 32;                                                   \
        _Pragma("unroll")                                                      \
        for (int i = 0; i < 4; i++) {                                          \
            int idx = t + i * 256; int r = idx >> 3; int c = (idx & 7) * 4;    \
            ra[i]  = *reinterpret_cast<const float4*>(                         \
                x + (size_t)(row0 + r) * DMODEL + k0_ + c);                    \
            rbv[i] = *reinterpret_cast<const float4*>(                         \
                W + (size_t)r * DMODEL + k0_ + c);                             \
        }                                                                      \
    }

#define QKV_STS(buf)                                                           \
    {                                                                          \
        unsigned* A_ = As + (buf) * QKV_BUFW;                                  \
        unsigned* B_ = Bs + (buf) * QKV_BUFW;                                  \
        _Pragma("unroll")                                                      \
        for (int i = 0; i < 4; i++) {                                          \
            int idx = t + i * 256; int r = idx >> 3; int c = (idx & 7) * 4;    \
            uint4 ua = make_uint4(f2tf(ra[i].x), f2tf(ra[i].y),                \
                                  f2tf(ra[i].z), f2tf(ra[i].w));               \
            uint4 ub = make_uint4(f2tf(rbv[i].x), f2tf(rbv[i].y),              \
                                  f2tf(rbv[i].z), f2tf(rbv[i].w));             \
            *reinterpret_cast<uint4*>(&A_[r * QKV_PITCH + c]) = ua;            \
            *reinterpret_cast<uint4*>(&B_[r * QKV_PITCH + c]) = ub;            \
        }                                                                      \
    }

    QKV_LOADG(0);
    QKV_STS(0);
    QKV_LOADG(1);
    __syncthreads();

    for (int kt = 0; kt < 32; kt++) {
        const int cur = kt & 1;
        if (kt + 1 < 32) QKV_STS(cur ^ 1);
        if (kt + 2 < 32) QKV_LOADG(kt + 2);

        const unsigned* A_ = As + cur * QKV_BUFW;
        const unsigned* B_ = Bs + cur * QKV_BUFW;
#pragma unroll
        for (int ks = 0; ks < 4; ks++) {
            const int kk = ks * 8;
            unsigned af[4][4], bf[4][2];
#pragma unroll
            for (int mf = 0; mf < 4; mf++) {
                int r = m0 + mf * 16 + g;
                af[mf][0] = A_[r * QKV_PITCH + kk + klo];
                af[mf][1] = A_[(r + 8) * QKV_PITCH + kk + klo];
                af[mf][2] = A_[r * QKV_PITCH + kk + klo + 4];
                af[mf][3] = A_[(r + 8) * QKV_PITCH + kk + klo + 4];
            }
#pragma unroll
            for (int nf = 0; nf < 4; nf++) {
                int n = n0 + nf * 8 + g;
                bf[nf][0] = B_[n * QKV_PITCH + kk + klo];
                bf[nf][1] = B_[n * QKV_PITCH + kk + klo + 4];
            }
#pragma unroll
            for (int mf = 0; mf < 4; mf++)
#pragma unroll
                for (int nf = 0; nf < 4; nf++) mma8(C[mf][nf], af[mf], bf[nf]);
        }
        __syncthreads();
    }

#pragma unroll
    for (int mf = 0; mf < 4; mf++)
#pragma unroll
        for (int nf = 0; nf < 4; nf++) {
            int r  = row0 + m0 + mf * 16 + g;
            int cc = n0 + nf * 8 + 2 * klo;
            *reinterpret_cast<float2*>(out + (size_t)r * HSIZE + cc) =
                make_float2(C[mf][nf][0], C[mf][nf][1]);
            *reinterpret_cast<float2*>(out + (size_t)(r + 8) * HSIZE + cc) =
                make_float2(C[mf][nf][2], C[mf][nf][3]);
        }
}

// ---------------------------------------------------------------------------
// Kernel 2: causal flash attention, tf32 tensor cores.
// CTA = 64 query rows; KV tiles of 64; 256 threads (8 warps).
// S gemm: warp grid (2M x 4N), warp tile 32x16.
// PV gemm: warp grid (2M x 4N), warp tile 32x32.
// All frag LDS patterns conflict-free by pitch choice (pitch mod 32 = 4 or 8).
// ---------------------------------------------------------------------------
#define QPIT 132   // mod 32 = 4
#define KPIT 132
#define VPIT 136   // mod 32 = 8 (B-frag reads k-major)
#define PPIT 68    // mod 32 = 4

#define ATTN_SMEM_WORDS (64 * QPIT + 64 * KPIT + 64 * VPIT + 64 * PPIT + 192)

__global__ __launch_bounds__(256, 1) void attn_kernel(float* __restrict__ out)
{
    extern __shared__ unsigned sm2[];
    unsigned* Qs = sm2;
    unsigned* Ks = Qs + 64 * QPIT;
    unsigned* Vs = Ks + 64 * KPIT;
    float* Ps   = reinterpret_cast<float*>(Vs + 64 * VPIT);
    float* mrow = Ps + 64 * PPIT;
    float* lrow = mrow + 64;
    float* arow = lrow + 64;

    const int b  = blockIdx.y;
    const int qt = 63 - blockIdx.x;          // heaviest tiles first
    const int q0 = qt * 64;

    const float* qb = g_q + ((size_t)b * TSEQ + q0) * HSIZE;
    const float* kb = g_k + (size_t)b * TSEQ * HSIZE;
    const float* vb = g_v + (size_t)b * TSEQ * HSIZE;

    const int t = threadIdx.x, warp = t >> 5, lane = t & 31;
    const int g = lane >> 2, klo = lane & 3;
    const int sm0 = (warp >> 2) * 32, sn0 = (warp & 3) * 16;  // S warp tile
    const int pm0 = sm0,              pn0 = (warp & 3) * 32;  // PV warp tile
    const float rscale = 0.08838834764831845f;   // 1/sqrt(128)

    // Load Q tile, fold softmax scale, convert tf32.
#pragma unroll
    for (int i = 0; i < 8; i++) {
        int idx = t + i * 256; int r = idx >> 5; int c = (idx & 31) * 4;
        float4 v = *reinterpret_cast<const float4*>(qb + (size_t)r * HSIZE + c);
        uint4 u = make_uint4(f2tf(v.x * rscale), f2tf(v.y * rscale),
                             f2tf(v.z * rscale), f2tf(v.w * rscale));
        *reinterpret_cast<uint4*>(&Qs[r * QPIT + c]) = u;
    }
    if (t < 64) { mrow[t] = -INFINITY; lrow[t] = 0.f; }

    float O[2][4][4];
#pragma unroll
    for (int mf = 0; mf < 2; mf++)
#pragma unroll
        for (int nf = 0; nf < 4; nf++)
#pragma unroll
            for (int cpos = 0; cpos < 4; cpos++) O[mf][nf][cpos] = 0.f;

    for (int j = 0; j <= qt; j++) {
        __syncthreads();   // prev iter done reading Ks/Vs/Ps
        const float* kt_ = kb + (size_t)j * 64 * HSIZE;
        const float* vt_ = vb + (size_t)j * 64 * HSIZE;
#pragma unroll
        for (int i = 0; i < 8; i++) {
            int idx = t + i * 256; int r = idx >> 5; int c = (idx & 31) * 4;
            float4 kv = *reinterpret_cast<const float4*>(kt_ + (size_t)r * HSIZE + c);
            float4 vv = *reinterpret_cast<const float4*>(vt_ + (size_t)r * HSIZE + c);
            *reinterpret_cast<uint4*>(&Ks[r * KPIT + c]) =
                make_uint4(f2tf(kv.x), f2tf(kv.y), f2tf(kv.z), f2tf(kv.w));
            *reinterpret_cast<uint4*>(&Vs[r * VPIT + c]) =
                make_uint4(f2tf(vv.x), f2tf(vv.y), f2tf(vv.z), f2tf(vv.w));
        }
        __syncthreads();

        // ---- S = Q K^T (64x64), warp tile 32x16 ----
        float SC[2][2][4];
#pragma unroll
        for (int mf = 0; mf < 2; mf++)
#pragma unroll
            for (int nf = 0; nf < 2; nf++)
#pragma unroll
                for (int cpos = 0; cpos < 4; cpos++) SC[mf][nf][cpos] = 0.f;

#pragma unroll
        for (int ks = 0; ks < 16; ks++) {
            const int kk = ks * 8;
            unsigned af[2][4], bf[2][2];
#pragma unroll
            for (int mf = 0; mf < 2; mf++) {
                int r = sm0 + mf * 16 + g;
                af[mf][0] = Qs[r * QPIT + kk + klo];
                af[mf][1] = Qs[(r + 8) * QPIT + kk + klo];
                af[mf][2] = Qs[r * QPIT + kk + klo + 4];
                af[mf][3] = Qs[(r + 8) * QPIT + kk + klo + 4];
            }
#pragma unroll
            for (int nf = 0; nf < 2; nf++) {
                int n = sn0 + nf * 8 + g;
                bf[nf][0] = Ks[n * KPIT + kk + klo];
                bf[nf][1] = Ks[n * KPIT + kk + klo + 4];
            }
#pragma unroll
            for (int mf = 0; mf < 2; mf++)
#pragma unroll
                for (int nf = 0; nf < 2; nf++) mma8(SC[mf][nf], af[mf], bf[nf]);
        }

        // Store S to smem with causal mask on the diagonal tile.
        const bool diag = (j == qt);
#pragma unroll
        for (int mf = 0; mf < 2; mf++)
#pragma unroll
            for (int nf = 0; nf < 2; nf++) {
                int r  = sm0 + mf * 16 + g;
                int cc = sn0 + nf * 8 + 2 * klo;
                float c0 = SC[mf][nf][0], c1 = SC[mf][nf][1];
                float c2 = SC[mf][nf][2], c3 = SC[mf][nf][3];
                if (diag) {
                    if (cc     > r)     c0 = -INFINITY;
                    if (cc + 1 > r)     c1 = -INFINITY;
                    if (cc     > r + 8) c2 = -INFINITY;
                    if (cc + 1 > r + 8) c3 = -INFINITY;
                }
                *reinterpret_cast<float2*>(&Ps[r * PPIT + cc]) = make_float2(c0, c1);
                *reinterpret_cast<float2*>(&Ps[(r + 8) * PPIT + cc]) = make_float2(c2, c3);
            }
        __syncthreads();

        // ---- online softmax: 4 threads per row ----
        {
            int r = t >> 2, sub = t & 3;
            float* row = Ps + r * PPIT + sub * 16;
            float mx = -INFINITY;
#pragma unroll
            for (int c = 0; c < 16; c++) mx = fmaxf(mx, row[c]);
            mx = fmaxf(mx, __shfl_xor_sync(0xffffffffu, mx, 1));
            mx = fmaxf(mx, __shfl_xor_sync(0xffffffffu, mx, 2));
            float mold = mrow[r];
            float mnew = fmaxf(mold, mx);
            float l = 0.f;
#pragma unroll
            for (int c = 0; c < 16; c++) {
                float p = __expf(row[c] - mnew);
                unsigned pu = f2tf(p);          // round to tf32 once...
                float pf = __uint_as_float(pu); // ...so PV and l agree exactly
                row[c] = pf;
                l += pf;
            }
            l += __shfl_xor_sync(0xffffffffu, l, 1);
            l += __shfl_xor_sync(0xffffffffu, l, 2);
            if (sub == 0) {
                float alpha = __expf(mold - mnew);
                arow[r] = alpha;
                lrow[r] = lrow[r] * alpha + l;
                mrow[r] = mnew;
            }
        }
        __syncthreads();

        // ---- rescale O, then O += P V (warp tile 32x32, K=64) ----
        float alA[2][2] = {{arow[pm0 + g], arow[pm0 + g + 8]},
                           {arow[pm0 + 16 + g], arow[pm0 + 24 + g]}};
#pragma unroll
        for (int mf = 0; mf < 2; mf++)
#pragma unroll
            for (int nf = 0; nf < 4; nf++) {
                O[mf][nf][0] *= alA[mf][0]; O[mf][nf][1] *= alA[mf][0];
                O[mf][nf][2] *= alA[mf][1]; O[mf][nf][3] *= alA[mf][1];
            }

#pragma unroll
        for (int ks = 0; ks < 8; ks++) {
            const int kk = ks * 8;
            unsigned af[2][4], bf[4][2];
#pragma unroll
            for (int mf = 0; mf < 2; mf++) {
                int r = pm0 + mf * 16 + g;
                af[mf][0] = __float_as_uint(Ps[r * PPIT + kk + klo]);
                af[mf][1] = __float_as_uint(Ps[(r + 8) * PPIT + kk + klo]);
                af[mf][2] = __float_as_uint(Ps[r * PPIT + kk + klo + 4]);
                af[mf][3] = __float_as_uint(Ps[(r + 8) * PPIT + kk + klo + 4]);
            }
#pragma unroll
            for (int nf = 0; nf < 4; nf++) {
                int n = pn0 + nf * 8 + g;
                bf[nf][0] = Vs[(kk + klo) * VPIT + n];
                bf[nf][1] = Vs[(kk + klo + 4) * VPIT + n];
            }
#pragma unroll
            for (int mf = 0; mf < 2; mf++)
#pragma unroll
                for (int nf = 0; nf < 4; nf++) mma8(O[mf][nf], af[mf], bf[nf]);
        }
    }

    // Epilogue: normalize by l and store.
#pragma unroll
    for (int mf = 0; mf < 2; mf++) {
        float inv0 = 1.f / lrow[pm0 + mf * 16 + g];
        float inv1 = 1.f / lrow[pm0 + mf * 16 + 8 + g];
#pragma unroll
        for (int nf = 0; nf < 4; nf++) {
            int r  = q0 + pm0 + mf * 16 + g;
            int cc = pn0 + nf * 8 + 2 * klo;
            float* op = out + (size_t)b * TSEQ * HSIZE;
            *reinterpret_cast<float2*>(op + (size_t)r * HSIZE + cc) =
                make_float2(O[mf][nf][0] * inv0, O[mf][nf][1] * inv0);
            *reinterpret_cast<float2*>(op + (size_t)(r + 8) * HSIZE + cc) =
                make_float2(O[mf][nf][2] * inv1, O[mf][nf][3] * inv1);
        }
    }
}

// ---------------------------------------------------------------------------
extern "C" void kernel_launch(void* const* d_in, const int* in_sizes, int n_in,
                              void* d_out, int out_size)
{
    const float* x  = (const float*)d_in[0];
    const float* Wq = (const float*)d_in[1];
    const float* Wk = (const float*)d_in[2];
    const float* Wv = (const float*)d_in[3];
    float* out = (float*)d_out;

    const int smem1 = 4 * QKV_BUFW * (int)sizeof(unsigned);
    cudaFuncSetAttribute(qkv_kernel,
                         cudaFuncAttributeMaxDynamicSharedMemorySize, smem1);
    qkv_kernel<<<dim3(3, NROWS / 128), 256, smem1>>>(x, Wq, Wk, Wv);

    const int smem2 = ATTN_SMEM_WORDS * (int)sizeof(unsigned);
    cudaFuncSetAttribute(attn_kernel,
                         cudaFuncAttributeMaxDynamicSharedMemorySize, smem2);
    attn_kernel<<<dim3(TSEQ / 64, NBATCH), 256, smem2>>>(out);
}

// round 5
// speedup vs baseline: 3.7542x; 1.1189x over previous
#include <cuda_runtime.h>
#include <math.h>

#define NBATCH 4
#define TSEQ   4096
#define DMODEL 1024
#define HSIZE  128
#define NROWS  (NBATCH * TSEQ)

__device__ float g_q[(size_t)NROWS * HSIZE];
__device__ float g_k[(size_t)NROWS * HSIZE];
__device__ float g_v[(size_t)NROWS * HSIZE];

__device__ __forceinline__ unsigned f2tf(float f) {
    unsigned u;
    asm("cvt.rna.tf32.f32 %0, %1;" : "=r"(u) : "f"(f));
    return u;
}

// D += A(16x8, row) * B(8x8, col), tf32 inputs, f32 accumulate.
__device__ __forceinline__ void mma8(float* c, const unsigned* a, const unsigned* b) {
    asm volatile(
        "mma.sync.aligned.m16n8k8.row.col.f32.tf32.tf32.f32 "
        "{%0,%1,%2,%3},{%4,%5,%6,%7},{%8,%9},{%0,%1,%2,%3};"
        : "+f"(c[0]), "+f"(c[1]), "+f"(c[2]), "+f"(c[3])
        : "r"(a[0]), "r"(a[1]), "r"(a[2]), "r"(a[3]), "r"(b[0]), "r"(b[1]));
}

// ---------------------------------------------------------------------------
// Kernel 1: QKV projection, tf32 tensor cores.
// ---------------------------------------------------------------------------
#define QKV_PITCH 36
#define QKV_BUFW  (128 * QKV_PITCH)

__global__ __launch_bounds__(256, 1) void qkv_kernel(
    const float* __restrict__ x,
    const float* __restrict__ Wq,
    const float* __restrict__ Wk,
    const float* __restrict__ Wv)
{
    extern __shared__ unsigned sm1[];
    unsigned* As = sm1;
    unsigned* Bs = sm1 + 2 * QKV_BUFW;

    const int w  = blockIdx.x;
    const int rb = blockIdx.y;
    const float* __restrict__ W = (w == 0) ? Wq : ((w == 1) ? Wk : Wv);
    float* out = (w == 0) ? g_q : ((w == 1) ? g_k : g_v);
    const int row0 = rb * 128;

    const int t = threadIdx.x;
    const int warp = t >> 5, lane = t & 31;
    const int g = lane >> 2, klo = lane & 3;
    const int m0 = (warp >> 2) * 64;
    const int n0 = (warp & 3) * 32;

    float C[4][4][4];
#pragma unroll
    for (int a = 0; a < 4; a++)
#pragma unroll
        for (int bb = 0; bb < 4; bb++)
#pragma unroll
            for (int cpos = 0; cpos < 4; cpos++) C[a][bb][cpos] = 0.f;

    float4 ra[4], rbv[4];

#define QKV_LOADG(kt)                                                          \
    {                                                                          \
        int k0_ = (kt) * 32;                                                   \
        _Pragma("unroll")                                                      \
        for (int i = 0; i < 4; i++) {                                          \
            int idx = t + i * 256; int r = idx >> 3; int c = (idx & 7) * 4;    \
            ra[i]  = *reinterpret_cast<const float4*>(                         \
                x + (size_t)(row0 + r) * DMODEL + k0_ + c);                    \
            rbv[i] = *reinterpret_cast<const float4*>(                         \
                W + (size_t)r * DMODEL + k0_ + c);                             \
        }                                                                      \
    }

#define QKV_STS(buf)                                                           \
    {                                                                          \
        unsigned* A_ = As + (buf) * QKV_BUFW;                                  \
        unsigned* B_ = Bs + (buf) * QKV_BUFW;                                  \
        _Pragma("unroll")                                                      \
        for (int i = 0; i < 4; i++) {                                          \
            int idx = t + i * 256; int r = idx >> 3; int c = (idx & 7) * 4;    \
            uint4 ua = make_uint4(f2tf(ra[i].x), f2tf(ra[i].y),                \
                                  f2tf(ra[i].z), f2tf(ra[i].w));               \
            uint4 ub = make_uint4(f2tf(rbv[i].x), f2tf(rbv[i].y),              \
                                  f2tf(rbv[i].z), f2tf(rbv[i].w));             \
            *reinterpret_cast<uint4*>(&A_[r * QKV_PITCH + c]) = ua;            \
            *reinterpret_cast<uint4*>(&B_[r * QKV_PITCH + c]) = ub;            \
        }                                                                      \
    }

    QKV_LOADG(0);
    QKV_STS(0);
    QKV_LOADG(1);
    __syncthreads();

    for (int kt = 0; kt < 32; kt++) {
        const int cur = kt & 1;
        if (kt + 1 < 32) QKV_STS(cur ^ 1);
        if (kt + 2 < 32) QKV_LOADG(kt + 2);

        const unsigned* A_ = As + cur * QKV_BUFW;
        const unsigned* B_ = Bs + cur * QKV_BUFW;
#pragma unroll
        for (int ks = 0; ks < 4; ks++) {
            const int kk = ks * 8;
            unsigned af[4][4], bf[4][2];
#pragma unroll
            for (int mf = 0; mf < 4; mf++) {
                int r = m0 + mf * 16 + g;
                af[mf][0] = A_[r * QKV_PITCH + kk + klo];
                af[mf][1] = A_[(r + 8) * QKV_PITCH + kk + klo];
                af[mf][2] = A_[r * QKV_PITCH + kk + klo + 4];
                af[mf][3] = A_[(r + 8) * QKV_PITCH + kk + klo + 4];
            }
#pragma unroll
            for (int nf = 0; nf < 4; nf++) {
                int n = n0 + nf * 8 + g;
                bf[nf][0] = B_[n * QKV_PITCH + kk + klo];
                bf[nf][1] = B_[n * QKV_PITCH + kk + klo + 4];
            }
#pragma unroll
            for (int mf = 0; mf < 4; mf++)
#pragma unroll
                for (int nf = 0; nf < 4; nf++) mma8(C[mf][nf], af[mf], bf[nf]);
        }
        __syncthreads();
    }

#pragma unroll
    for (int mf = 0; mf < 4; mf++)
#pragma unroll
        for (int nf = 0; nf < 4; nf++) {
            int r  = row0 + m0 + mf * 16 + g;
            int cc = n0 + nf * 8 + 2 * klo;
            *reinterpret_cast<float2*>(out + (size_t)r * HSIZE + cc) =
                make_float2(C[mf][nf][0], C[mf][nf][1]);
            *reinterpret_cast<float2*>(out + (size_t)(r + 8) * HSIZE + cc) =
                make_float2(C[mf][nf][2], C[mf][nf][3]);
        }
}

// ---------------------------------------------------------------------------
// Kernel 2: causal flash attention, tf32, register softmax + double-buffered
// K/V (register prefetch -> tf32 STS). 2 barriers per KV tile.
// K prefetch issues before the S-gemm; V prefetch before the softmax
// (staggered to cap live-register pressure; both land before barrier #2).
// ---------------------------------------------------------------------------
#define QPIT 132   // mod 32 = 4
#define KPIT 132
#define VPIT 136   // mod 32 = 8
#define PPIT 68    // mod 32 = 4
#define KBUF (64 * KPIT)
#define VBUF (64 * VPIT)

#define ATTN_SMEM_WORDS (64 * QPIT + 2 * KBUF + 2 * VBUF + 64 * PPIT + 256)

__global__ __launch_bounds__(256, 1) void attn_kernel(float* __restrict__ out)
{
    extern __shared__ unsigned sm2[];
    unsigned* Qs = sm2;
    unsigned* Ks = Qs + 64 * QPIT;          // [2][64][KPIT]
    unsigned* Vs = Ks + 2 * KBUF;           // [2][64][VPIT]
    float* Ps    = reinterpret_cast<float*>(Vs + 2 * VBUF);
    float* pmax  = Ps + 64 * PPIT;          // [64][4] (reused as psum in epilogue)

    const int b  = blockIdx.y;
    const int qt = 63 - blockIdx.x;          // heaviest tiles first
    const int q0 = qt * 64;

    const float* qb = g_q + ((size_t)b * TSEQ + q0) * HSIZE;
    const float* kb = g_k + (size_t)b * TSEQ * HSIZE;
    const float* vb = g_v + (size_t)b * TSEQ * HSIZE;

    const int t = threadIdx.x, warp = t >> 5, lane = t & 31;
    const int g = lane >> 2, klo = lane & 3;
    const int sm0 = (warp >> 2) * 32, sn0 = (warp & 3) * 16;  // S warp tile
    const int pn0 = (warp & 3) * 32;                          // PV warp tile N
    const float rscale = 0.08838834764831845f;   // 1/sqrt(128)

    // Load Q tile, fold softmax scale, convert tf32.
#pragma unroll
    for (int i = 0; i < 8; i++) {
        int idx = t + i * 256; int r = idx >> 5; int c = (idx & 31) * 4;
        float4 v = *reinterpret_cast<const float4*>(qb + (size_t)r * HSIZE + c);
        *reinterpret_cast<uint4*>(&Qs[r * QPIT + c]) =
            make_uint4(f2tf(v.x * rscale), f2tf(v.y * rscale),
                       f2tf(v.z * rscale), f2tf(v.w * rscale));
    }
    // Preload KV tile 0 into buffer 0.
#pragma unroll
    for (int i = 0; i < 8; i++) {
        int idx = t + i * 256; int r = idx >> 5; int c = (idx & 31) * 4;
        float4 kv = *reinterpret_cast<const float4*>(kb + (size_t)r * HSIZE + c);
        float4 vv = *reinterpret_cast<const float4*>(vb + (size_t)r * HSIZE + c);
        *reinterpret_cast<uint4*>(&Ks[r * KPIT + c]) =
            make_uint4(f2tf(kv.x), f2tf(kv.y), f2tf(kv.z), f2tf(kv.w));
        *reinterpret_cast<uint4*>(&Vs[r * VPIT + c]) =
            make_uint4(f2tf(vv.x), f2tf(vv.y), f2tf(vv.z), f2tf(vv.w));
    }

    // Per-thread online-softmax state, all registers.
    float O[2][4][4];
    float mold[2][2], lpart[2][2];
#pragma unroll
    for (int mf = 0; mf < 2; mf++) {
#pragma unroll
        for (int nf = 0; nf < 4; nf++)
#pragma unroll
            for (int cpos = 0; cpos < 4; cpos++) O[mf][nf][cpos] = 0.f;
        mold[mf][0] = -INFINITY; mold[mf][1] = -INFINITY;
        lpart[mf][0] = 0.f;      lpart[mf][1] = 0.f;
    }
    __syncthreads();

    float4 kr[8], vr[8];

    for (int j = 0; j <= qt; j++) {
        const int buf = j & 1;
        const unsigned* K_ = Ks + buf * KBUF;
        const unsigned* V_ = Vs + buf * VBUF;
        const bool pf = (j < qt);

        // Prefetch next K tile into registers (overlaps with S-gemm).
        if (pf) {
            const float* kn = kb + (size_t)(j + 1) * 64 * HSIZE;
#pragma unroll
            for (int i = 0; i < 8; i++) {
                int idx = t + i * 256; int r = idx >> 5; int c = (idx & 31) * 4;
                kr[i] = *reinterpret_cast<const float4*>(kn + (size_t)r * HSIZE + c);
            }
        }

        // ---- S = Q K^T (64x64), warp tile 32x16 ----
        float SC[2][2][4];
#pragma unroll
        for (int mf = 0; mf < 2; mf++)
#pragma unroll
            for (int nf = 0; nf < 2; nf++)
#pragma unroll
                for (int cpos = 0; cpos < 4; cpos++) SC[mf][nf][cpos] = 0.f;

#pragma unroll
        for (int ks = 0; ks < 16; ks++) {
            const int kk = ks * 8;
            unsigned af[2][4], bf[2][2];
#pragma unroll
            for (int mf = 0; mf < 2; mf++) {
                int r = sm0 + mf * 16 + g;
                af[mf][0] = Qs[r * QPIT + kk + klo];
                af[mf][1] = Qs[(r + 8) * QPIT + kk + klo];
                af[mf][2] = Qs[r * QPIT + kk + klo + 4];
                af[mf][3] = Qs[(r + 8) * QPIT + kk + klo + 4];
            }
#pragma unroll
            for (int nf = 0; nf < 2; nf++) {
                int n = sn0 + nf * 8 + g;
                bf[nf][0] = K_[n * KPIT + kk + klo];
                bf[nf][1] = K_[n * KPIT + kk + klo + 4];
            }
#pragma unroll
            for (int mf = 0; mf < 2; mf++)
#pragma unroll
                for (int nf = 0; nf < 2; nf++) mma8(SC[mf][nf], af[mf], bf[nf]);
        }

        // Prefetch next V tile (overlaps with softmax; consumed after barrier #2).
        if (pf) {
            const float* vn = vb + (size_t)(j + 1) * 64 * HSIZE;
#pragma unroll
            for (int i = 0; i < 8; i++) {
                int idx = t + i * 256; int r = idx >> 5; int c = (idx & 31) * 4;
                vr[i] = *reinterpret_cast<const float4*>(vn + (size_t)r * HSIZE + c);
            }
        }

        // Causal mask on the diagonal tile (in registers).
        if (j == qt) {
#pragma unroll
            for (int mf = 0; mf < 2; mf++)
#pragma unroll
                for (int nf = 0; nf < 2; nf++) {
                    int r  = sm0 + mf * 16 + g;
                    int cc = sn0 + nf * 8 + 2 * klo;
                    if (cc     > r)     SC[mf][nf][0] = -INFINITY;
                    if (cc + 1 > r)     SC[mf][nf][1] = -INFINITY;
                    if (cc     > r + 8) SC[mf][nf][2] = -INFINITY;
                    if (cc + 1 > r + 8) SC[mf][nf][3] = -INFINITY;
                }
        }

        // ---- row max: in-quad shuffle reduce, then cross-warp via pmax ----
#pragma unroll
        for (int mf = 0; mf < 2; mf++) {
            float p0 = fmaxf(fmaxf(SC[mf][0][0], SC[mf][0][1]),
                             fmaxf(SC[mf][1][0], SC[mf][1][1]));
            float p1 = fmaxf(fmaxf(SC[mf][0][2], SC[mf][0][3]),
                             fmaxf(SC[mf][1][2], SC[mf][1][3]));
            p0 = fmaxf(p0, __shfl_xor_sync(0xffffffffu, p0, 1));
            p0 = fmaxf(p0, __shfl_xor_sync(0xffffffffu, p0, 2));
            p1 = fmaxf(p1, __shfl_xor_sync(0xffffffffu, p1, 1));
            p1 = fmaxf(p1, __shfl_xor_sync(0xffffffffu, p1, 2));
            if (klo == 0) {
                pmax[(sm0 + mf * 16 + g) * 4 + (warp & 3)] = p0;
                pmax[(sm0 + mf * 16 + 8 + g) * 4 + (warp & 3)] = p1;
            }
        }
        __syncthreads();   // barrier #1

        // ---- mnew/alpha (registers), exp, P store, l update, O rescale ----
        float alpha[2][2];
#pragma unroll
        for (int mf = 0; mf < 2; mf++)
#pragma unroll
            for (int half = 0; half < 2; half++) {
                int r = sm0 + mf * 16 + half * 8 + g;
                float4 pv = *reinterpret_cast<const float4*>(&pmax[r * 4]);
                float mnew = fmaxf(mold[mf][half],
                                   fmaxf(fmaxf(pv.x, pv.y), fmaxf(pv.z, pv.w)));
                alpha[mf][half] = __expf(mold[mf][half] - mnew);
                mold[mf][half] = mnew;
            }

#pragma unroll
        for (int mf = 0; mf < 2; mf++) {
            float s0 = 0.f, s1 = 0.f;
#pragma unroll
            for (int nf = 0; nf < 2; nf++) {
                int r  = sm0 + mf * 16 + g;
                int cc = sn0 + nf * 8 + 2 * klo;
                float p0 = __uint_as_float(f2tf(__expf(SC[mf][nf][0] - mold[mf][0])));
                float p1 = __uint_as_float(f2tf(__expf(SC[mf][nf][1] - mold[mf][0])));
                float p2 = __uint_as_float(f2tf(__expf(SC[mf][nf][2] - mold[mf][1])));
                float p3 = __uint_as_float(f2tf(__expf(SC[mf][nf][3] - mold[mf][1])));
                s0 += p0 + p1;
                s1 += p2 + p3;
                *reinterpret_cast<float2*>(&Ps[r * PPIT + cc]) = make_float2(p0, p1);
                *reinterpret_cast<float2*>(&Ps[(r + 8) * PPIT + cc]) = make_float2(p2, p3);
            }
            lpart[mf][0] = lpart[mf][0] * alpha[mf][0] + s0;
            lpart[mf][1] = lpart[mf][1] * alpha[mf][1] + s1;
        }

#pragma unroll
        for (int mf = 0; mf < 2; mf++)
#pragma unroll
            for (int nf = 0; nf < 4; nf++) {
                O[mf][nf][0] *= alpha[mf][0]; O[mf][nf][1] *= alpha[mf][0];
                O[mf][nf][2] *= alpha[mf][1]; O[mf][nf][3] *= alpha[mf][1];
            }

        // Drain the prefetched KV tile into the alternate buffers.
        if (pf) {
            unsigned* Kn = Ks + (buf ^ 1) * KBUF;
            unsigned* Vn = Vs + (buf ^ 1) * VBUF;
#pragma unroll
            for (int i = 0; i < 8; i++) {
                int idx = t + i * 256; int r = idx >> 5; int c = (idx & 31) * 4;
                *reinterpret_cast<uint4*>(&Kn[r * KPIT + c]) =
                    make_uint4(f2tf(kr[i].x), f2tf(kr[i].y), f2tf(kr[i].z), f2tf(kr[i].w));
                *reinterpret_cast<uint4*>(&Vn[r * VPIT + c]) =
                    make_uint4(f2tf(vr[i].x), f2tf(vr[i].y), f2tf(vr[i].z), f2tf(vr[i].w));
            }
        }
        __syncthreads();   // barrier #2

        // ---- O += P V (warp tile 32x32, K=64) ----
#pragma unroll
        for (int ks = 0; ks < 8; ks++) {
            const int kk = ks * 8;
            unsigned af[2][4], bf[4][2];
#pragma unroll
            for (int mf = 0; mf < 2; mf++) {
                int r = sm0 + mf * 16 + g;
                af[mf][0] = __float_as_uint(Ps[r * PPIT + kk + klo]);
                af[mf][1] = __float_as_uint(Ps[(r + 8) * PPIT + kk + klo]);
                af[mf][2] = __float_as_uint(Ps[r * PPIT + kk + klo + 4]);
                af[mf][3] = __float_as_uint(Ps[(r + 8) * PPIT + kk + klo + 4]);
            }
#pragma unroll
            for (int nf = 0; nf < 4; nf++) {
                int n = pn0 + nf * 8 + g;
                bf[nf][0] = V_[(kk + klo) * VPIT + n];
                bf[nf][1] = V_[(kk + klo + 4) * VPIT + n];
            }
#pragma unroll
            for (int mf = 0; mf < 2; mf++)
#pragma unroll
                for (int nf = 0; nf < 4; nf++) mma8(O[mf][nf], af[mf], bf[nf]);
        }
    }

    // ---- epilogue: reduce l across quad + warps, normalize, store ----
#pragma unroll
    for (int mf = 0; mf < 2; mf++)
#pragma unroll
        for (int half = 0; half < 2; half++) {
            float v = lpart[mf][half];
            v += __shfl_xor_sync(0xffffffffu, v, 1);
            v += __shfl_xor_sync(0xffffffffu, v, 2);
            if (klo == 0)
                pmax[(sm0 + mf * 16 + half * 8 + g) * 4 + (warp & 3)] = v;
        }
    __syncthreads();

#pragma unroll
    for (int mf = 0; mf < 2; mf++) {
        float4 s0 = *reinterpret_cast<const float4*>(&pmax[(sm0 + mf * 16 + g) * 4]);
        float4 s1 = *reinterpret_cast<const float4*>(&pmax[(sm0 + mf * 16 + 8 + g) * 4]);
        float inv0 = 1.f / (s0.x + s0.y + s0.z + s0.w);
        float inv1 = 1.f / (s1.x + s1.y + s1.z + s1.w);
#pragma unroll
        for (int nf = 0; nf < 4; nf++) {
            int r  = q0 + sm0 + mf * 16 + g;
            int cc = pn0 + nf * 8 + 2 * klo;
            float* op = out + (size_t)b * TSEQ * HSIZE;
            *reinterpret_cast<float2*>(op + (size_t)r * HSIZE + cc) =
                make_float2(O[mf][nf][0] * inv0, O[mf][nf][1] * inv0);
            *reinterpret_cast<float2*>(op + (size_t)(r + 8) * HSIZE + cc) =
                make_float2(O[mf][nf][2] * inv1, O[mf][nf][3] * inv1);
        }
    }
}

// ---------------------------------------------------------------------------
extern "C" void kernel_launch(void* const* d_in, const int* in_sizes, int n_in,
                              void* d_out, int out_size)
{
    const float* x  = (const float*)d_in[0];
    const float* Wq = (const float*)d_in[1];
    const float* Wk = (const float*)d_in[2];
    const float* Wv = (const float*)d_in[3];
    float* out = (float*)d_out;

    const int smem1 = 4 * QKV_BUFW * (int)sizeof(unsigned);
    cudaFuncSetAttribute(qkv_kernel,
                         cudaFuncAttributeMaxDynamicSharedMemorySize, smem1);
    qkv_kernel<<<dim3(3, NROWS / 128), 256, smem1>>>(x, Wq, Wk, Wv);

    const int smem2 = ATTN_SMEM_WORDS * (int)sizeof(unsigned);
    cudaFuncSetAttribute(attn_kernel,
                         cudaFuncAttributeMaxDynamicSharedMemorySize, smem2);
    attn_kernel<<<dim3(TSEQ / 64, NBATCH), 256, smem2>>>(out);
}

// round 7
// speedup vs baseline: 6.1947x; 1.6501x over previous
#include <cuda_runtime.h>
#include <cuda_fp16.h>
#include <math.h>
#include <stdint.h>

#define NBATCH 4
#define TSEQ   4096
#define DMODEL 1024
#define HSIZE  128
#define NROWS  (NBATCH * TSEQ)

__device__ float g_q[(size_t)NROWS * HSIZE];
__device__ float g_k[(size_t)NROWS * HSIZE];
__device__ float g_v[(size_t)NROWS * HSIZE];

// ---------------------------------------------------------------------------
// Helpers
// ---------------------------------------------------------------------------
__device__ __forceinline__ uint32_t smem_u32(const void* p) {
    uint32_t a;
    asm("{ .reg .u64 t; cvta.to.shared.u64 t, %1; cvt.u32.u64 %0, t; }"
        : "=r"(a) : "l"(p));
    return a;
}

__device__ __forceinline__ uint32_t f2h2(float a, float b) {
    __half2 h = __floats2half2_rn(a, b);
    return *reinterpret_cast<uint32_t*>(&h);
}

// D += A(16x16) * B(16x8), fp16 inputs, f32 accumulate.
__device__ __forceinline__ void mma16(float* c, const uint32_t* a, const uint32_t* b) {
    asm volatile(
        "mma.sync.aligned.m16n8k16.row.col.f32.f16.f16.f32 "
        "{%0,%1,%2,%3},{%4,%5,%6,%7},{%8,%9},{%0,%1,%2,%3};"
        : "+f"(c[0]), "+f"(c[1]), "+f"(c[2]), "+f"(c[3])
        : "r"(a[0]), "r"(a[1]), "r"(a[2]), "r"(a[3]), "r"(b[0]), "r"(b[1]));
}

__device__ __forceinline__ void ldm4(uint32_t* r, uint32_t a) {
    asm volatile("ldmatrix.sync.aligned.m8n8.x4.shared.b16 {%0,%1,%2,%3}, [%4];"
                 : "=r"(r[0]), "=r"(r[1]), "=r"(r[2]), "=r"(r[3]) : "r"(a));
}
__device__ __forceinline__ void ldm4t(uint32_t* r, uint32_t a) {
    asm volatile("ldmatrix.sync.aligned.m8n8.x4.trans.shared.b16 {%0,%1,%2,%3}, [%4];"
                 : "=r"(r[0]), "=r"(r[1]), "=r"(r[2]), "=r"(r[3]) : "r"(a));
}

// ---------------------------------------------------------------------------
// Kernel 1: QKV projection, fp16 mma.sync (m16n8k16) + ldmatrix.
// C[128,128] per CTA = x[128,1024] * W[128,1024]^T.  BK=32, double-buffered.
// smem rows: 32 halves + 8 pad = 80 bytes pitch (80*k mod 128 spans all 16B
// groups -> conflict-free ldmatrix).
// ---------------------------------------------------------------------------
#define QKV_PITCH_B 80
#define QKV_TILE_B  (128 * QKV_PITCH_B)        // 10240 bytes per operand tile
#define QKV_STAGE_B (2 * QKV_TILE_B)           // A + B
#define QKV_SMEM    (2 * QKV_STAGE_B)          // two stages (40960 B)

__global__ __launch_bounds__(256, 1) void qkv_kernel(
    const float* __restrict__ x,
    const float* __restrict__ Wq,
    const float* __restrict__ Wk,
    const float* __restrict__ Wv)
{
    extern __shared__ char sm1[];
    const uint32_t sbase = smem_u32(sm1);

    const int w  = blockIdx.x;
    const int rb = blockIdx.y;
    const float* __restrict__ W = (w == 0) ? Wq : ((w == 1) ? Wk : Wv);
    float* out = (w == 0) ? g_q : ((w == 1) ? g_k : g_v);
    const int row0 = rb * 128;

    const int t = threadIdx.x;
    const int warp = t >> 5, lane = t & 31;
    const int g = lane >> 2, klo = lane & 3;
    const int l8 = lane & 7, qd = lane >> 3;
    const int m0 = (warp >> 2) * 64;
    const int n0 = (warp & 3) * 32;

    // ldmatrix base row offsets (bytes, within a tile)
    uint32_t arow[4], brow[2];
#pragma unroll
    for (int mf = 0; mf < 4; mf++)
        arow[mf] = (uint32_t)((m0 + mf * 16 + (qd & 1) * 8 + l8) * QKV_PITCH_B
                              + (qd >> 1) * 16);
#pragma unroll
    for (int p = 0; p < 2; p++)
        brow[p] = (uint32_t)((n0 + p * 16 + (qd >> 1) * 8 + l8) * QKV_PITCH_B
                             + (qd & 1) * 16);

    float C[4][4][4];
#pragma unroll
    for (int a = 0; a < 4; a++)
#pragma unroll
        for (int bb = 0; bb < 4; bb++)
#pragma unroll
            for (int cp = 0; cp < 4; cp++) C[a][bb][cp] = 0.f;

    float4 ra[4], rbv[4];
    const int lr = t >> 3, lc = (t & 7) * 4;    // load coords: row, col(halves)

#define QKV_LOADG(kt)                                                          \
    {                                                                          \
        int k0_ = (kt) * 32;                                                   \
        _Pragma("unroll")                                                      \
        for (int i = 0; i < 4; i++) {                                          \
            int r = lr + i * 32;                                               \
            ra[i]  = *reinterpret_cast<const float4*>(                         \
                x + (size_t)(row0 + r) * DMODEL + k0_ + lc);                   \
            rbv[i] = *reinterpret_cast<const float4*>(                         \
                W + (size_t)r * DMODEL + k0_ + lc);                            \
        }                                                                      \
    }

#define QKV_STS(buf)                                                           \
    {                                                                          \
        char* A_ = sm1 + (buf) * QKV_STAGE_B;                                  \
        char* B_ = A_ + QKV_TILE_B;                                            \
        _Pragma("unroll")                                                      \
        for (int i = 0; i < 4; i++) {                                          \
            int r = lr + i * 32;                                               \
            uint32_t bo = (uint32_t)(r * QKV_PITCH_B + lc * 2);                \
            *reinterpret_cast<uint2*>(A_ + bo) =                               \
                make_uint2(f2h2(ra[i].x, ra[i].y), f2h2(ra[i].z, ra[i].w));    \
            *reinterpret_cast<uint2*>(B_ + bo) =                               \
                make_uint2(f2h2(rbv[i].x, rbv[i].y), f2h2(rbv[i].z, rbv[i].w));\
        }                                                                      \
    }

    QKV_LOADG(0);
    QKV_STS(0);
    QKV_LOADG(1);
    __syncthreads();

    for (int kt = 0; kt < 32; kt++) {
        const int cur = kt & 1;
        if (kt + 1 < 32) QKV_STS(cur ^ 1);
        if (kt + 2 < 32) QKV_LOADG(kt + 2);

        const uint32_t Ab = sbase + cur * QKV_STAGE_B;
        const uint32_t Bb = Ab + QKV_TILE_B;
#pragma unroll
        for (int ks = 0; ks < 2; ks++) {
            uint32_t af[4][4], bf[2][4];
#pragma unroll
            for (int mf = 0; mf < 4; mf++) ldm4(af[mf], Ab + arow[mf] + ks * 32);
#pragma unroll
            for (int p = 0; p < 2; p++)    ldm4(bf[p], Bb + brow[p] + ks * 32);
#pragma unroll
            for (int mf = 0; mf < 4; mf++) {
                mma16(C[mf][0], af[mf], bf[0]);
                mma16(C[mf][1], af[mf], bf[0] + 2);
                mma16(C[mf][2], af[mf], bf[1]);
                mma16(C[mf][3], af[mf], bf[1] + 2);
            }
        }
        __syncthreads();
    }

#pragma unroll
    for (int mf = 0; mf < 4; mf++)
#pragma unroll
        for (int nf = 0; nf < 4; nf++) {
            int r  = row0 + m0 + mf * 16 + g;
            int cc = n0 + nf * 8 + 2 * klo;
            *reinterpret_cast<float2*>(out + (size_t)r * HSIZE + cc) =
                make_float2(C[mf][nf][0], C[mf][nf][1]);
            *reinterpret_cast<float2*>(out + (size_t)(r + 8) * HSIZE + cc) =
                make_float2(C[mf][nf][2], C[mf][nf][3]);
        }
}

// ---------------------------------------------------------------------------
// Kernel 2: causal flash attention, fp16 mma.sync + ldmatrix.
// 64 q-rows/CTA, 64-key tiles, 256 threads.  Register softmax, double-buffered
// K/V via register prefetch, 2 barriers per tile.
// Word (4B) layout: Q[64][68] | K[2][64][68] | V[2][64][68] | P[64][36] | pmax[256]
// ---------------------------------------------------------------------------
#define QPW   68               // row pitch in words (64 half2 + 4 pad)
#define PPW   36               // P row pitch in words (32 half2 + 4)
#define QW    (64 * QPW)
#define KOFF  QW
#define VOFF  (QW + 2 * QW)
#define POFF  (QW + 4 * QW)
#define PMOFF (POFF + 64 * PPW)
#define ATTN_SMEM_WORDS (PMOFF + 256)

__global__ __launch_bounds__(256, 1) void attn_kernel(float* __restrict__ out)
{
    extern __shared__ uint32_t sm2[];
    uint32_t* Qs = sm2;
    uint32_t* Ks = sm2 + KOFF;
    uint32_t* Vs = sm2 + VOFF;
    uint32_t* Ps = sm2 + POFF;
    float* pmax  = reinterpret_cast<float*>(sm2 + PMOFF);
    const uint32_t sbase = smem_u32(sm2);

    const int b  = blockIdx.y;
    const int qt = 63 - blockIdx.x;          // heaviest tiles first
    const int q0 = qt * 64;

    const float* qb = g_q + ((size_t)b * TSEQ + q0) * HSIZE;
    const float* kb = g_k + (size_t)b * TSEQ * HSIZE;
    const float* vb = g_v + (size_t)b * TSEQ * HSIZE;

    const int t = threadIdx.x, warp = t >> 5, lane = t & 31;
    const int g = lane >> 2, klo = lane & 3;
    const int l8 = lane & 7, qd = lane >> 3;
    const int sm0 = (warp >> 2) * 32, sn0 = (warp & 3) * 16;  // S warp tile
    const int pn0 = (warp & 3) * 32;                          // PV warp tile N
    const float rscale = 0.08838834764831845f;   // 1/sqrt(128)

    // ldmatrix row offsets (in words)
    uint32_t qrow[2], prow[2];
#pragma unroll
    for (int mf = 0; mf < 2; mf++) {
        const int r = sm0 + mf * 16 + (qd & 1) * 8 + l8;
        qrow[mf] = (uint32_t)(r * QPW + (qd >> 1) * 4);
        prow[mf] = (uint32_t)(r * PPW + (qd >> 1) * 4);
    }
    const uint32_t krow = (uint32_t)((sn0 + (qd >> 1) * 8 + l8) * QPW + (qd & 1) * 4);
    const uint32_t vrow = (uint32_t)(((qd & 1) * 8 + l8) * QPW + pn0 / 2 + (qd >> 1) * 4);

    // Load Q tile, fold softmax scale, cvt fp16.
#pragma unroll
    for (int i = 0; i < 8; i++) {
        int idx = t + i * 256; int r = idx >> 5; int c = (idx & 31) * 4;
        float4 v = *reinterpret_cast<const float4*>(qb + (size_t)r * HSIZE + c);
        *reinterpret_cast<uint2*>(&Qs[r * QPW + c / 2]) =
            make_uint2(f2h2(v.x * rscale, v.y * rscale),
                       f2h2(v.z * rscale, v.w * rscale));
    }
    // Preload KV tile 0 into buffer 0.
#pragma unroll
    for (int i = 0; i < 8; i++) {
        int idx = t + i * 256; int r = idx >> 5; int c = (idx & 31) * 4;
        float4 kv = *reinterpret_cast<const float4*>(kb + (size_t)r * HSIZE + c);
        float4 vv = *reinterpret_cast<const float4*>(vb + (size_t)r * HSIZE + c);
        *reinterpret_cast<uint2*>(&Ks[r * QPW + c / 2]) =
            make_uint2(f2h2(kv.x, kv.y), f2h2(kv.z, kv.w));
        *reinterpret_cast<uint2*>(&Vs[r * QPW + c / 2]) =
            make_uint2(f2h2(vv.x, vv.y), f2h2(vv.z, vv.w));
    }

    float O[2][4][4];
    float mold[2][2], lpart[2][2];
#pragma unroll
    for (int mf = 0; mf < 2; mf++) {
#pragma unroll
        for (int nf = 0; nf < 4; nf++)
#pragma unroll
            for (int cp = 0; cp < 4; cp++) O[mf][nf][cp] = 0.f;
        mold[mf][0] = -INFINITY; mold[mf][1] = -INFINITY;
        lpart[mf][0] = 0.f;      lpart[mf][1] = 0.f;
    }
    __syncthreads();

    float4 kr[8], vr[8];

    for (int j = 0; j <= qt; j++) {
        const int buf = j & 1;
        const uint32_t Kb = sbase + (KOFF + buf * QW) * 4;
        const uint32_t Vb = sbase + (VOFF + buf * QW) * 4;
        const uint32_t Pb = sbase + POFF * 4;
        const bool pf = (j < qt);

        // Prefetch next K tile into registers (overlaps with S-gemm).
        if (pf) {
            const float* kn = kb + (size_t)(j + 1) * 64 * HSIZE;
#pragma unroll
            for (int i = 0; i < 8; i++) {
                int idx = t + i * 256; int r = idx >> 5; int c = (idx & 31) * 4;
                kr[i] = *reinterpret_cast<const float4*>(kn + (size_t)r * HSIZE + c);
            }
        }

        // ---- S = Q K^T (64x64), warp tile 32x16 ----
        float SC[2][2][4];
#pragma unroll
        for (int mf = 0; mf < 2; mf++)
#pragma unroll
            for (int nf = 0; nf < 2; nf++)
#pragma unroll
                for (int cp = 0; cp < 4; cp++) SC[mf][nf][cp] = 0.f;

#pragma unroll
        for (int ks = 0; ks < 8; ks++) {
            uint32_t a0[4], a1[4], bf[4];
            ldm4(a0, sbase + (qrow[0] + 8 * ks) * 4);
            ldm4(a1, sbase + (qrow[1] + 8 * ks) * 4);
            ldm4(bf, Kb + (krow + 8 * ks) * 4);
            mma16(SC[0][0], a0, bf);
            mma16(SC[0][1], a0, bf + 2);
            mma16(SC[1][0], a1, bf);
            mma16(SC[1][1], a1, bf + 2);
        }

        // Prefetch next V tile (consumed after barrier #2).
        if (pf) {
            const float* vn = vb + (size_t)(j + 1) * 64 * HSIZE;
#pragma unroll
            for (int i = 0; i < 8; i++) {
                int idx = t + i * 256; int r = idx >> 5; int c = (idx & 31) * 4;
                vr[i] = *reinterpret_cast<const float4*>(vn + (size_t)r * HSIZE + c);
            }
        }

        // Causal mask on the diagonal tile.
        if (j == qt) {
#pragma unroll
            for (int mf = 0; mf < 2; mf++)
#pragma unroll
                for (int nf = 0; nf < 2; nf++) {
                    int r  = sm0 + mf * 16 + g;
                    int cc = sn0 + nf * 8 + 2 * klo;
                    if (cc     > r)     SC[mf][nf][0] = -INFINITY;
                    if (cc + 1 > r)     SC[mf][nf][1] = -INFINITY;
                    if (cc     > r + 8) SC[mf][nf][2] = -INFINITY;
                    if (cc + 1 > r + 8) SC[mf][nf][3] = -INFINITY;
                }
        }

        // ---- row max: quad shuffle + cross-warp via pmax ----
#pragma unroll
        for (int mf = 0; mf < 2; mf++) {
            float p0 = fmaxf(fmaxf(SC[mf][0][0], SC[mf][0][1]),
                             fmaxf(SC[mf][1][0], SC[mf][1][1]));
            float p1 = fmaxf(fmaxf(SC[mf][0][2], SC[mf][0][3]),
                             fmaxf(SC[mf][1][2], SC[mf][1][3]));
            p0 = fmaxf(p0, __shfl_xor_sync(0xffffffffu, p0, 1));
            p0 = fmaxf(p0, __shfl_xor_sync(0xffffffffu, p0, 2));
            p1 = fmaxf(p1, __shfl_xor_sync(0xffffffffu, p1, 1));
            p1 = fmaxf(p1, __shfl_xor_sync(0xffffffffu, p1, 2));
            if (klo == 0) {
                pmax[(sm0 + mf * 16 + g) * 4 + (warp & 3)] = p0;
                pmax[(sm0 + mf * 16 + 8 + g) * 4 + (warp & 3)] = p1;
            }
        }
        __syncthreads();   // barrier #1

        // ---- softmax (registers), P -> smem fp16, O rescale ----
        float alpha[2][2];
#pragma unroll
        for (int mf = 0; mf < 2; mf++)
#pragma unroll
            for (int half = 0; half < 2; half++) {
                int r = sm0 + mf * 16 + half * 8 + g;
                float4 pv = *reinterpret_cast<const float4*>(&pmax[r * 4]);
                float mnew = fmaxf(mold[mf][half],
                                   fmaxf(fmaxf(pv.x, pv.y), fmaxf(pv.z, pv.w)));
                alpha[mf][half] = __expf(mold[mf][half] - mnew);
                mold[mf][half] = mnew;
            }

#pragma unroll
        for (int mf = 0; mf < 2; mf++) {
            float s0 = 0.f, s1 = 0.f;
#pragma unroll
            for (int nf = 0; nf < 2; nf++) {
                int r  = sm0 + mf * 16 + g;
                int cw = sn0 / 2 + nf * 4 + klo;         // half2 word in P row
                __half h0 = __float2half_rn(__expf(SC[mf][nf][0] - mold[mf][0]));
                __half h1 = __float2half_rn(__expf(SC[mf][nf][1] - mold[mf][0]));
                __half h2 = __float2half_rn(__expf(SC[mf][nf][2] - mold[mf][1]));
                __half h3 = __float2half_rn(__expf(SC[mf][nf][3] - mold[mf][1]));
                s0 += __half2float(h0) + __half2float(h1);
                s1 += __half2float(h2) + __half2float(h3);
                __half2 p01 = __halves2half2(h0, h1), p23 = __halves2half2(h2, h3);
                Ps[r * PPW + cw]       = *reinterpret_cast<uint32_t*>(&p01);
                Ps[(r + 8) * PPW + cw] = *reinterpret_cast<uint32_t*>(&p23);
            }
            lpart[mf][0] = lpart[mf][0] * alpha[mf][0] + s0;
            lpart[mf][1] = lpart[mf][1] * alpha[mf][1] + s1;
        }

#pragma unroll
        for (int mf = 0; mf < 2; mf++)
#pragma unroll
            for (int nf = 0; nf < 4; nf++) {
                O[mf][nf][0] *= alpha[mf][0]; O[mf][nf][1] *= alpha[mf][0];
                O[mf][nf][2] *= alpha[mf][1]; O[mf][nf][3] *= alpha[mf][1];
            }

        // Drain prefetched KV into the alternate buffers.
        if (pf) {
            uint32_t* Kn = Ks + (buf ^ 1) * QW;
            uint32_t* Vn = Vs + (buf ^ 1) * QW;
#pragma unroll
            for (int i = 0; i < 8; i++) {
                int idx = t + i * 256; int r = idx >> 5; int c = (idx & 31) * 4;
                *reinterpret_cast<uint2*>(&Kn[r * QPW + c / 2]) =
                    make_uint2(f2h2(kr[i].x, kr[i].y), f2h2(kr[i].z, kr[i].w));
                *reinterpret_cast<uint2*>(&Vn[r * QPW + c / 2]) =
                    make_uint2(f2h2(vr[i].x, vr[i].y), f2h2(vr[i].z, vr[i].w));
            }
        }
        __syncthreads();   // barrier #2

        // ---- O += P V (warp tile 32x32, K=64) ----
#pragma unroll
        for (int ks = 0; ks < 4; ks++) {
            uint32_t pa0[4], pa1[4], v0[4], v1[4];
            ldm4(pa0, Pb + (prow[0] + 8 * ks) * 4);
            ldm4(pa1, Pb + (prow[1] + 8 * ks) * 4);
            ldm4t(v0, Vb + (vrow + (uint32_t)(16 * ks) * QPW) * 4);
            ldm4t(v1, Vb + (vrow + (uint32_t)(16 * ks) * QPW + 8) * 4);
            mma16(O[0][0], pa0, v0); mma16(O[0][1], pa0, v0 + 2);
            mma16(O[0][2], pa0, v1); mma16(O[0][3], pa0, v1 + 2);
            mma16(O[1][0], pa1, v0); mma16(O[1][1], pa1, v0 + 2);
            mma16(O[1][2], pa1, v1); mma16(O[1][3], pa1, v1 + 2);
        }
    }

    // ---- epilogue: reduce l, normalize, store ----
#pragma unroll
    for (int mf = 0; mf < 2; mf++)
#pragma unroll
        for (int half = 0; half < 2; half++) {
            float v = lpart[mf][half];
            v += __shfl_xor_sync(0xffffffffu, v, 1);
            v += __shfl_xor_sync(0xffffffffu, v, 2);
            if (klo == 0)
                pmax[(sm0 + mf * 16 + half * 8 + g) * 4 + (warp & 3)] = v;
        }
    __syncthreads();

#pragma unroll
    for (int mf = 0; mf < 2; mf++) {
        float4 s0 = *reinterpret_cast<const float4*>(&pmax[(sm0 + mf * 16 + g) * 4]);
        float4 s1 = *reinterpret_cast<const float4*>(&pmax[(sm0 + mf * 16 + 8 + g) * 4]);
        float inv0 = 1.f / (s0.x + s0.y + s0.z + s0.w);
        float inv1 = 1.f / (s1.x + s1.y + s1.z + s1.w);
#pragma unroll
        for (int nf = 0; nf < 4; nf++) {
            int r  = q0 + sm0 + mf * 16 + g;
            int cc = pn0 + nf * 8 + 2 * klo;
            float* op = out + (size_t)b * TSEQ * HSIZE;
            *reinterpret_cast<float2*>(op + (size_t)r * HSIZE + cc) =
                make_float2(O[mf][nf][0] * inv0, O[mf][nf][1] * inv0);
            *reinterpret_cast<float2*>(op + (size_t)(r + 8) * HSIZE + cc) =
                make_float2(O[mf][nf][2] * inv1, O[mf][nf][3] * inv1);
        }
    }
}

// ---------------------------------------------------------------------------
extern "C" void kernel_launch(void* const* d_in, const int* in_sizes, int n_in,
                              void* d_out, int out_size)
{
    const float* x  = (const float*)d_in[0];
    const float* Wq = (const float*)d_in[1];
    const float* Wk = (const float*)d_in[2];
    const float* Wv = (const float*)d_in[3];
    float* out = (float*)d_out;

    cudaFuncSetAttribute(qkv_kernel,
                         cudaFuncAttributeMaxDynamicSharedMemorySize, QKV_SMEM);
    qkv_kernel<<<dim3(3, NROWS / 128), 256, QKV_SMEM>>>(x, Wq, Wk, Wv);

    const int smem2 = ATTN_SMEM_WORDS * 4;
    cudaFuncSetAttribute(attn_kernel,
                         cudaFuncAttributeMaxDynamicSharedMemorySize, smem2);
    attn_kernel<<<dim3(TSEQ / 64, NBATCH), 256, smem2>>>(out);
}

// round 8
// speedup vs baseline: 7.7855x; 1.2568x over previous
#include <cuda_runtime.h>
#include <cuda_fp16.h>
#include <math.h>
#include <stdint.h>

#define NBATCH 4
#define TSEQ   4096
#define DMODEL 1024
#define HSIZE  128
#define NROWS  (NBATCH * TSEQ)

// q/k/v live in global as fp16 (rounded once, same point as before).
__device__ __align__(16) __half g_q[(size_t)NROWS * HSIZE];
__device__ __align__(16) __half g_k[(size_t)NROWS * HSIZE];
__device__ __align__(16) __half g_v[(size_t)NROWS * HSIZE];

// ---------------------------------------------------------------------------
// Helpers
// ---------------------------------------------------------------------------
__device__ __forceinline__ uint32_t smem_u32(const void* p) {
    uint32_t a;
    asm("{ .reg .u64 t; cvta.to.shared.u64 t, %1; cvt.u32.u64 %0, t; }"
        : "=r"(a) : "l"(p));
    return a;
}

__device__ __forceinline__ uint32_t f2h2(float a, float b) {
    __half2 h = __floats2half2_rn(a, b);
    return *reinterpret_cast<uint32_t*>(&h);
}

__device__ __forceinline__ void mma16(float* c, const uint32_t* a, const uint32_t* b) {
    asm volatile(
        "mma.sync.aligned.m16n8k16.row.col.f32.f16.f16.f32 "
        "{%0,%1,%2,%3},{%4,%5,%6,%7},{%8,%9},{%0,%1,%2,%3};"
        : "+f"(c[0]), "+f"(c[1]), "+f"(c[2]), "+f"(c[3])
        : "r"(a[0]), "r"(a[1]), "r"(a[2]), "r"(a[3]), "r"(b[0]), "r"(b[1]));
}

__device__ __forceinline__ void ldm4(uint32_t* r, uint32_t a) {
    asm volatile("ldmatrix.sync.aligned.m8n8.x4.shared.b16 {%0,%1,%2,%3}, [%4];"
                 : "=r"(r[0]), "=r"(r[1]), "=r"(r[2]), "=r"(r[3]) : "r"(a));
}
__device__ __forceinline__ void ldm4t(uint32_t* r, uint32_t a) {
    asm volatile("ldmatrix.sync.aligned.m8n8.x4.trans.shared.b16 {%0,%1,%2,%3}, [%4];"
                 : "=r"(r[0]), "=r"(r[1]), "=r"(r[2]), "=r"(r[3]) : "r"(a));
}

#define CPA16(dst, src) \
    asm volatile("cp.async.cg.shared.global [%0], [%1], 16;" \
                 :: "r"(dst), "l"(src) : "memory")
#define CPA_COMMIT() asm volatile("cp.async.commit_group;" ::: "memory")
#define CPA_WAIT0()  asm volatile("cp.async.wait_group 0;" ::: "memory")

// ---------------------------------------------------------------------------
// Kernel 1: QKV projection, fp16 mma.sync + ldmatrix, fp16 output.
// Wq is pre-scaled by 1/sqrt(128) so q needs no scaling downstream.
// ---------------------------------------------------------------------------
#define QKV_PITCH_B 80
#define QKV_TILE_B  (128 * QKV_PITCH_B)
#define QKV_STAGE_B (2 * QKV_TILE_B)
#define QKV_SMEM    (2 * QKV_STAGE_B)

__global__ __launch_bounds__(256, 1) void qkv_kernel(
    const float* __restrict__ x,
    const float* __restrict__ Wq,
    const float* __restrict__ Wk,
    const float* __restrict__ Wv)
{
    extern __shared__ char sm1[];
    const uint32_t sbase = smem_u32(sm1);

    const int w  = blockIdx.x;
    const int rb = blockIdx.y;
    const float* __restrict__ W = (w == 0) ? Wq : ((w == 1) ? Wk : Wv);
    __half* out = (w == 0) ? g_q : ((w == 1) ? g_k : g_v);
    const float ws = (w == 0) ? 0.08838834764831845f : 1.0f;
    const int row0 = rb * 128;

    const int t = threadIdx.x;
    const int warp = t >> 5, lane = t & 31;
    const int g = lane >> 2, klo = lane & 3;
    const int l8 = lane & 7, qd = lane >> 3;
    const int m0 = (warp >> 2) * 64;
    const int n0 = (warp & 3) * 32;

    uint32_t arow[4], brow[2];
#pragma unroll
    for (int mf = 0; mf < 4; mf++)
        arow[mf] = (uint32_t)((m0 + mf * 16 + (qd & 1) * 8 + l8) * QKV_PITCH_B
                              + (qd >> 1) * 16);
#pragma unroll
    for (int p = 0; p < 2; p++)
        brow[p] = (uint32_t)((n0 + p * 16 + (qd >> 1) * 8 + l8) * QKV_PITCH_B
                             + (qd & 1) * 16);

    float C[4][4][4];
#pragma unroll
    for (int a = 0; a < 4; a++)
#pragma unroll
        for (int bb = 0; bb < 4; bb++)
#pragma unroll
            for (int cp = 0; cp < 4; cp++) C[a][bb][cp] = 0.f;

    float4 ra[4], rbv[4];
    const int lr = t >> 3, lc = (t & 7) * 4;

#define QKV_LOADG(kt)                                                          \
    {                                                                          \
        int k0_ = (kt) * 32;                                                   \
        _Pragma("unroll")                                                      \
        for (int i = 0; i < 4; i++) {                                          \
            int r = lr + i * 32;                                               \
            ra[i]  = *reinterpret_cast<const float4*>(                         \
                x + (size_t)(row0 + r) * DMODEL + k0_ + lc);                   \
            rbv[i] = *reinterpret_cast<const float4*>(                         \
                W + (size_t)r * DMODEL + k0_ + lc);                            \
        }                                                                      \
    }

#define QKV_STS(buf)                                                           \
    {                                                                          \
        char* A_ = sm1 + (buf) * QKV_STAGE_B;                                  \
        char* B_ = A_ + QKV_TILE_B;                                            \
        _Pragma("unroll")                                                      \
        for (int i = 0; i < 4; i++) {                                          \
            int r = lr + i * 32;                                               \
            uint32_t bo = (uint32_t)(r * QKV_PITCH_B + lc * 2);                \
            *reinterpret_cast<uint2*>(A_ + bo) =                               \
                make_uint2(f2h2(ra[i].x, ra[i].y), f2h2(ra[i].z, ra[i].w));    \
            *reinterpret_cast<uint2*>(B_ + bo) =                               \
                make_uint2(f2h2(rbv[i].x * ws, rbv[i].y * ws),                 \
                           f2h2(rbv[i].z * ws, rbv[i].w * ws));                \
        }                                                                      \
    }

    QKV_LOADG(0);
    QKV_STS(0);
    QKV_LOADG(1);
    __syncthreads();

    for (int kt = 0; kt < 32; kt++) {
        const int cur = kt & 1;
        if (kt + 1 < 32) QKV_STS(cur ^ 1);
        if (kt + 2 < 32) QKV_LOADG(kt + 2);

        const uint32_t Ab = sbase + cur * QKV_STAGE_B;
        const uint32_t Bb = Ab + QKV_TILE_B;
#pragma unroll
        for (int ks = 0; ks < 2; ks++) {
            uint32_t af[4][4], bf[2][4];
#pragma unroll
            for (int mf = 0; mf < 4; mf++) ldm4(af[mf], Ab + arow[mf] + ks * 32);
#pragma unroll
            for (int p = 0; p < 2; p++)    ldm4(bf[p], Bb + brow[p] + ks * 32);
#pragma unroll
            for (int mf = 0; mf < 4; mf++) {
                mma16(C[mf][0], af[mf], bf[0]);
                mma16(C[mf][1], af[mf], bf[0] + 2);
                mma16(C[mf][2], af[mf], bf[1]);
                mma16(C[mf][3], af[mf], bf[1] + 2);
            }
        }
        __syncthreads();
    }

#pragma unroll
    for (int mf = 0; mf < 4; mf++)
#pragma unroll
        for (int nf = 0; nf < 4; nf++) {
            int r  = row0 + m0 + mf * 16 + g;
            int cc = n0 + nf * 8 + 2 * klo;
            *reinterpret_cast<__half2*>(out + (size_t)r * HSIZE + cc) =
                __floats2half2_rn(C[mf][nf][0], C[mf][nf][1]);
            *reinterpret_cast<__half2*>(out + (size_t)(r + 8) * HSIZE + cc) =
                __floats2half2_rn(C[mf][nf][2], C[mf][nf][3]);
        }
}

// ---------------------------------------------------------------------------
// Kernel 2: causal flash attention, fp16 + ldmatrix + cp.async, 2 CTAs/SM.
// SMEM (bytes): Q 0..16K | K 2x16K | V 2x16K | P 8K | pmax 1K  = 89K
// XOR swizzle: chunk' = chunk ^ (row & 7) on 16B chunks (conflict-free for
// cp.async STS, ldmatrix (trans and non-trans), and the P half2 stores).
// ---------------------------------------------------------------------------
#define ATT_QOFF  0
#define ATT_KOFF  16384
#define ATT_VOFF  49152
#define ATT_POFF  81920
#define ATT_PMOFF 90112
#define ATT_SMEM  91136

__global__ __launch_bounds__(256, 2) void attn_kernel(float* __restrict__ out)
{
    extern __shared__ __align__(16) char smc[];
    const uint32_t sb = smem_u32(smc);
    float* pmax   = reinterpret_cast<float*>(smc + ATT_PMOFF);
    uint32_t* Pw  = reinterpret_cast<uint32_t*>(smc + ATT_POFF);

    // bid -> (batch, qt) permutation: co-resident pairs (bid, bid+148) get
    // complementary work so per-SM tile counts are balanced in one wave.
    const int bid = blockIdx.x;
    const int rnk = (bid < 148) ? bid : 403 - bid;
    const int b   = rnk & 3;
    const int qt  = 63 - (rnk >> 2);
    const int q0  = qt * 64;

    const __half* qb = g_q + ((size_t)b * TSEQ + q0) * HSIZE;
    const __half* kb = g_k + (size_t)b * TSEQ * HSIZE;
    const __half* vb = g_v + (size_t)b * TSEQ * HSIZE;

    const int t = threadIdx.x, warp = t >> 5, lane = t & 31;
    const int g = lane >> 2, klo = lane & 3;
    const int l8 = lane & 7, qd = lane >> 3;
    const int sm0 = (warp >> 2) * 32, sn0 = (warp & 3) * 16;
    const int pn0 = (warp & 3) * 32;

    // Issue Q + KV tile 0 copies.
#pragma unroll
    for (int i = 0; i < 4; i++) {
        int lin = t + i * 256; int row = lin >> 4, ch = lin & 15;
        uint32_t dsw = (uint32_t)(row * 256 + ((ch ^ (row & 7)) << 4));
        CPA16(sb + ATT_QOFF + dsw, qb + row * 128 + ch * 8);
        CPA16(sb + ATT_KOFF + dsw, kb + row * 128 + ch * 8);
        CPA16(sb + ATT_VOFF + dsw, vb + row * 128 + ch * 8);
    }
    CPA_COMMIT();

    // Per-lane ldmatrix constants (row & 7 == l8 for every pattern below).
    const int rq0 = sm0 + (qd & 1) * 8 + l8;   // Q/P A-frag rows (mf=0; +16 mf=1)
    const int cqa = qd >> 1;
    const int rk0 = sn0 + (qd >> 1) * 8 + l8;  // K B-frag rows
    const int ckb = qd & 1;
    const int rv0 = (qd & 1) * 8 + l8;         // V rows base
    const int cv0 = (pn0 >> 3) + (qd >> 1);    // V chunk base

    const uint32_t Qb = sb + ATT_QOFF;
    const uint32_t Pb = sb + ATT_POFF;

    float O[2][4][4];
    float mold[2][2], lpart[2][2];
#pragma unroll
    for (int mf = 0; mf < 2; mf++) {
#pragma unroll
        for (int nf = 0; nf < 4; nf++)
#pragma unroll
            for (int cp = 0; cp < 4; cp++) O[mf][nf][cp] = 0.f;
        mold[mf][0] = -INFINITY; mold[mf][1] = -INFINITY;
        lpart[mf][0] = 0.f;      lpart[mf][1] = 0.f;
    }

    CPA_WAIT0();
    __syncthreads();

    for (int j = 0; j <= qt; j++) {
        const int buf = j & 1;
        const uint32_t Kb = sb + ATT_KOFF + buf * 16384;
        const uint32_t Vb = sb + ATT_VOFF + buf * 16384;

        // ---- S = Q K^T (64x64) ----
        float SC[2][2][4];
#pragma unroll
        for (int mf = 0; mf < 2; mf++)
#pragma unroll
            for (int nf = 0; nf < 2; nf++)
#pragma unroll
                for (int cp = 0; cp < 4; cp++) SC[mf][nf][cp] = 0.f;

#pragma unroll
        for (int ks = 0; ks < 8; ks++) {
            uint32_t a0[4], a1[4], bf[4];
            ldm4(a0, Qb + rq0 * 256 + (((2 * ks + cqa) ^ l8) << 4));
            ldm4(a1, Qb + (rq0 + 16) * 256 + (((2 * ks + cqa) ^ l8) << 4));
            ldm4(bf, Kb + rk0 * 256 + (((2 * ks + ckb) ^ l8) << 4));
            mma16(SC[0][0], a0, bf);
            mma16(SC[0][1], a0, bf + 2);
            mma16(SC[1][0], a1, bf);
            mma16(SC[1][1], a1, bf + 2);
        }

        // Causal mask on the diagonal tile.
        if (j == qt) {
#pragma unroll
            for (int mf = 0; mf < 2; mf++)
#pragma unroll
                for (int nf = 0; nf < 2; nf++) {
                    int r  = sm0 + mf * 16 + g;
                    int cc = sn0 + nf * 8 + 2 * klo;
                    if (cc     > r)     SC[mf][nf][0] = -INFINITY;
                    if (cc + 1 > r)     SC[mf][nf][1] = -INFINITY;
                    if (cc     > r + 8) SC[mf][nf][2] = -INFINITY;
                    if (cc + 1 > r + 8) SC[mf][nf][3] = -INFINITY;
                }
        }

        // ---- row max: quad shuffle + cross-warp via pmax ----
#pragma unroll
        for (int mf = 0; mf < 2; mf++) {
            float p0 = fmaxf(fmaxf(SC[mf][0][0], SC[mf][0][1]),
                             fmaxf(SC[mf][1][0], SC[mf][1][1]));
            float p1 = fmaxf(fmaxf(SC[mf][0][2], SC[mf][0][3]),
                             fmaxf(SC[mf][1][2], SC[mf][1][3]));
            p0 = fmaxf(p0, __shfl_xor_sync(0xffffffffu, p0, 1));
            p0 = fmaxf(p0, __shfl_xor_sync(0xffffffffu, p0, 2));
            p1 = fmaxf(p1, __shfl_xor_sync(0xffffffffu, p1, 1));
            p1 = fmaxf(p1, __shfl_xor_sync(0xffffffffu, p1, 2));
            if (klo == 0) {
                pmax[(sm0 + mf * 16 + g) * 4 + (warp & 3)] = p0;
                pmax[(sm0 + mf * 16 + 8 + g) * 4 + (warp & 3)] = p1;
            }
        }
        __syncthreads();   // barrier 1 (also: all threads done with PV(j-1))

        // Prefetch KV tile j+1 into the alternate buffers (overlaps softmax+PV).
        if (j < qt) {
            const __half* kn = kb + (size_t)(j + 1) * 64 * HSIZE;
            const __half* vn = vb + (size_t)(j + 1) * 64 * HSIZE;
            const uint32_t Knb = sb + ATT_KOFF + (buf ^ 1) * 16384;
            const uint32_t Vnb = sb + ATT_VOFF + (buf ^ 1) * 16384;
#pragma unroll
            for (int i = 0; i < 4; i++) {
                int lin = t + i * 256; int row = lin >> 4, ch = lin & 15;
                uint32_t dsw = (uint32_t)(row * 256 + ((ch ^ (row & 7)) << 4));
                CPA16(Knb + dsw, kn + row * 128 + ch * 8);
                CPA16(Vnb + dsw, vn + row * 128 + ch * 8);
            }
            CPA_COMMIT();
        }

        // ---- softmax (registers), P -> smem fp16 (swizzled), O rescale ----
        float alpha[2][2];
#pragma unroll
        for (int mf = 0; mf < 2; mf++)
#pragma unroll
            for (int half = 0; half < 2; half++) {
                int r = sm0 + mf * 16 + half * 8 + g;
                float4 pv = *reinterpret_cast<const float4*>(&pmax[r * 4]);
                float mnew = fmaxf(mold[mf][half],
                                   fmaxf(fmaxf(pv.x, pv.y), fmaxf(pv.z, pv.w)));
                alpha[mf][half] = __expf(mold[mf][half] - mnew);
                mold[mf][half] = mnew;
            }

#pragma unroll
        for (int mf = 0; mf < 2; mf++) {
            float s0 = 0.f, s1 = 0.f;
#pragma unroll
            for (int nf = 0; nf < 2; nf++) {
                int r  = sm0 + mf * 16 + g;
                int cw = sn0 / 2 + nf * 4 + klo;       // half2 word, 0..31
                __half h0 = __float2half_rn(__expf(SC[mf][nf][0] - mold[mf][0]));
                __half h1 = __float2half_rn(__expf(SC[mf][nf][1] - mold[mf][0]));
                __half h2 = __float2half_rn(__expf(SC[mf][nf][2] - mold[mf][1]));
                __half h3 = __float2half_rn(__expf(SC[mf][nf][3] - mold[mf][1]));
                s0 += __half2float(h0) + __half2float(h1);
                s1 += __half2float(h2) + __half2float(h3);
                __half2 p01 = __halves2half2(h0, h1), p23 = __halves2half2(h2, h3);
                int w0 = r * 32 + (((cw >> 2) ^ (r & 7)) << 2) + (cw & 3);
                int w1 = (r + 8) * 32 + (((cw >> 2) ^ ((r + 8) & 7)) << 2) + (cw & 3);
                Pw[w0] = *reinterpret_cast<uint32_t*>(&p01);
                Pw[w1] = *reinterpret_cast<uint32_t*>(&p23);
            }
            lpart[mf][0] = lpart[mf][0] * alpha[mf][0] + s0;
            lpart[mf][1] = lpart[mf][1] * alpha[mf][1] + s1;
        }

#pragma unroll
        for (int mf = 0; mf < 2; mf++)
#pragma unroll
            for (int nf = 0; nf < 4; nf++) {
                O[mf][nf][0] *= alpha[mf][0]; O[mf][nf][1] *= alpha[mf][0];
                O[mf][nf][2] *= alpha[mf][1]; O[mf][nf][3] *= alpha[mf][1];
            }
        __syncthreads();   // barrier 2 (P visible to all warps)

        // ---- O += P V (warp tile 32x32, K=64) ----
#pragma unroll
        for (int ks = 0; ks < 4; ks++) {
            uint32_t pa0[4], pa1[4], v0[4], v1[4];
            ldm4(pa0, Pb + rq0 * 128 + (((2 * ks + cqa) ^ l8) << 4));
            ldm4(pa1, Pb + (rq0 + 16) * 128 + (((2 * ks + cqa) ^ l8) << 4));
            ldm4t(v0, Vb + (rv0 + 16 * ks) * 256 + ((cv0 ^ l8) << 4));
            ldm4t(v1, Vb + (rv0 + 16 * ks) * 256 + (((cv0 + 2) ^ l8) << 4));
            mma16(O[0][0], pa0, v0); mma16(O[0][1], pa0, v0 + 2);
            mma16(O[0][2], pa0, v1); mma16(O[0][3], pa0, v1 + 2);
            mma16(O[1][0], pa1, v0); mma16(O[1][1], pa1, v0 + 2);
            mma16(O[1][2], pa1, v1); mma16(O[1][3], pa1, v1 + 2);
        }

        // Tiles j+1 landed; make visible to all threads.
        CPA_WAIT0();
        __syncthreads();   // barrier 3
    }

    // ---- epilogue: reduce l, normalize, store ----
#pragma unroll
    for (int mf = 0; mf < 2; mf++)
#pragma unroll
        for (int half = 0; half < 2; half++) {
            float v = lpart[mf][half];
            v += __shfl_xor_sync(0xffffffffu, v, 1);
            v += __shfl_xor_sync(0xffffffffu, v, 2);
            if (klo == 0)
                pmax[(sm0 + mf * 16 + half * 8 + g) * 4 + (warp & 3)] = v;
        }
    __syncthreads();

#pragma unroll
    for (int mf = 0; mf < 2; mf++) {
        float4 s0 = *reinterpret_cast<const float4*>(&pmax[(sm0 + mf * 16 + g) * 4]);
        float4 s1 = *reinterpret_cast<const float4*>(&pmax[(sm0 + mf * 16 + 8 + g) * 4]);
        float inv0 = 1.f / (s0.x + s0.y + s0.z + s0.w);
        float inv1 = 1.f / (s1.x + s1.y + s1.z + s1.w);
#pragma unroll
        for (int nf = 0; nf < 4; nf++) {
            int r  = q0 + sm0 + mf * 16 + g;
            int cc = pn0 + nf * 8 + 2 * klo;
            float* op = out + (size_t)b * TSEQ * HSIZE;
            *reinterpret_cast<float2*>(op + (size_t)r * HSIZE + cc) =
                make_float2(O[mf][nf][0] * inv0, O[mf][nf][1] * inv0);
            *reinterpret_cast<float2*>(op + (size_t)(r + 8) * HSIZE + cc) =
                make_float2(O[mf][nf][2] * inv1, O[mf][nf][3] * inv1);
        }
    }
}

// ---------------------------------------------------------------------------
extern "C" void kernel_launch(void* const* d_in, const int* in_sizes, int n_in,
                              void* d_out, int out_size)
{
    const float* x  = (const float*)d_in[0];
    const float* Wq = (const float*)d_in[1];
    const float* Wk = (const float*)d_in[2];
    const float* Wv = (const float*)d_in[3];
    float* out = (float*)d_out;

    cudaFuncSetAttribute(qkv_kernel,
                         cudaFuncAttributeMaxDynamicSharedMemorySize, QKV_SMEM);
    qkv_kernel<<<dim3(3, NROWS / 128), 256, QKV_SMEM>>>(x, Wq, Wk, Wv);

    cudaFuncSetAttribute(attn_kernel,
                         cudaFuncAttributeMaxDynamicSharedMemorySize, ATT_SMEM);
    attn_kernel<<<256, 256, ATT_SMEM>>>(out);
}